// round 1
// baseline (speedup 1.0000x reference)
#include <cuda_runtime.h>

// RandomShiftsAug: the bilinear grid-sample in the reference degenerates to an
// exact integer pixel shift (ix = i + sx, iy = j + sy, weights == 0), so the
// output is a shifted copy with edge-clamp (the 'edge' pad mode):
//   out[n,c,j,i] = x[n,c, clamp(j + sy - PAD, 0, H-1), clamp(i + sx - PAD, 0, W-1)]
// shift layout: (N,1,1,2) int32, [...,0] = sx (width), [...,1] = sy (height).

#define C_ 4
#define H_ 84
#define W_ 84
#define PAD_ 4
#define W4_ (W_ / 4)   // 21 float4 per row; rows are 336B = 16B-aligned

__global__ void __launch_bounds__(256) shift_copy_kernel(
    const float* __restrict__ x,
    const int*   __restrict__ shift,
    float*       __restrict__ out,
    int total4)
{
    int idx = blockIdx.x * blockDim.x + threadIdx.x;
    if (idx >= total4) return;

    // idx enumerates float4 slots in output order (n, c, j, w4)
    int w4 = idx % W4_;
    int t  = idx / W4_;
    int j  = t % H_;
    int nc = t / H_;            // n*C_ + c
    int n  = nc / C_;

    int sx = __ldg(shift + 2 * n + 0) - PAD_;
    int sy = __ldg(shift + 2 * n + 1) - PAD_;

    int ys = j + sy;
    ys = min(max(ys, 0), H_ - 1);

    const float* row = x + ((long long)nc * H_ + ys) * W_;

    int i0 = w4 * 4;
    int x0 = min(max(i0 + 0 + sx, 0), W_ - 1);
    int x1 = min(max(i0 + 1 + sx, 0), W_ - 1);
    int x2 = min(max(i0 + 2 + sx, 0), W_ - 1);
    int x3 = min(max(i0 + 3 + sx, 0), W_ - 1);

    float4 v;
    v.x = __ldg(row + x0);
    v.y = __ldg(row + x1);
    v.z = __ldg(row + x2);
    v.w = __ldg(row + x3);

    reinterpret_cast<float4*>(out)[idx] = v;
}

extern "C" void kernel_launch(void* const* d_in, const int* in_sizes, int n_in,
                              void* d_out, int out_size)
{
    const float* x     = (const float*)d_in[0];
    const int*   shift = (const int*)d_in[1];
    float*       out   = (float*)d_out;

    int n = in_sizes[0] / (C_ * H_ * W_);
    int total4 = n * C_ * H_ * W4_;

    int threads = 256;
    int blocks  = (total4 + threads - 1) / threads;
    shift_copy_kernel<<<blocks, threads>>>(x, shift, out, total4);
}